// round 4
// baseline (speedup 1.0000x reference)
#include <cuda_runtime.h>
#include <cstdint>

// ---------------------------------------------------------------------------
// TractBundle: out = concat( x_a @ (Wa*Ma)^T, x_b @ (Wb*Mb)^T, x_c @ (Wc*Mc)^T )
// Masks: 64/64/32-sparse per row -> compressed sparse-gather, cp.async pipeline.
// S must be EVEN: all float2 smem accesses sit at word offset row*S + 2*lane.
// ---------------------------------------------------------------------------

#define CHUNK 256                   // src elements staged per pass
#define S     66                    // smem row stride (EVEN: float2 alignment)
#define TOKS  64                    // tokens per block (2 per lane, float2)
#define NDST  512                   // dst columns per block
#define DPW   16                    // dsts per warp
#define BUFW  (CHUNK * S)           // 16896 floats per buffer
#define SMEM_BYTES (2 * BUFW * 4)   // 135168

// Compressed tables: entry = ( (src&255)*66 , bits(w*m) ).
// Splits transposed: spl[p * n_dst + dst], cumulative entry counts.
__device__ __align__(16) int2 g_tabA[1024 * 64];
__device__ __align__(16) int2 g_tabB[512 * 64];
__device__ __align__(16) int2 g_tabC[512 * 32];
__device__ int g_splA[17 * 1024];
__device__ int g_splB[17 * 512];
__device__ int g_splC[9 * 512];

__device__ __forceinline__ void cp_async4(float* smem_dst, const float* gmem_src) {
    unsigned sa = (unsigned)__cvta_generic_to_shared(smem_dst);
    asm volatile("cp.async.ca.shared.global [%0], [%1], 4;" :: "r"(sa), "l"(gmem_src));
}
__device__ __forceinline__ void cp_commit() {
    asm volatile("cp.async.commit_group;" ::: "memory");
}
__device__ __forceinline__ void cp_wait1() {
    asm volatile("cp.async.wait_group 1;" ::: "memory");
}
__device__ __forceinline__ void cp_wait0() {
    asm volatile("cp.async.wait_group 0;" ::: "memory");
}

// ---------------------------------------------------------------------------
// Merged prep: one warp per dst row across all three tracts (2048 warp-rows).
// ---------------------------------------------------------------------------
__global__ void prep_all(const float* __restrict__ wa, const float* __restrict__ ma,
                         const float* __restrict__ wb, const float* __restrict__ mb,
                         const float* __restrict__ wc, const float* __restrict__ mc)
{
    int g    = (blockIdx.x * blockDim.x + threadIdx.x) >> 5;
    int lane = threadIdx.x & 31;

    const float *W, *M; int2* tab; int* spl;
    int src, n_dst, conn, row;
    if (g < 1024)      { W = wa; M = ma; tab = g_tabA; spl = g_splA;
                         src = 4096; n_dst = 1024; conn = 64; row = g; }
    else if (g < 1536) { W = wb; M = mb; tab = g_tabB; spl = g_splB;
                         src = 4096; n_dst = 512;  conn = 64; row = g - 1024; }
    else               { W = wc; M = mc; tab = g_tabC; spl = g_splC;
                         src = 2048; n_dst = 512;  conn = 32; row = g - 1536; }

    const float* wr = W + (size_t)row * src;
    const float* mr = M + (size_t)row * src;
    int2* trow = tab + (size_t)row * conn;

    if (lane == 0) spl[row] = 0;            // p = 0
    int cnt = 0;
    for (int s0 = 0; s0 < src; s0 += 32) {
        int s = s0 + lane;
        float mv = mr[s];
        unsigned bits = __ballot_sync(0xffffffffu, mv != 0.0f);
        if (mv != 0.0f) {
            int pos = cnt + __popc(bits & ((1u << lane) - 1u));
            trow[pos] = make_int2((s & (CHUNK - 1)) * S, __float_as_int(wr[s] * mv));
        }
        cnt += __popc(bits);
        int s_end = s0 + 32;
        if ((s_end & (CHUNK - 1)) == 0 && lane == 0)
            spl[(s_end >> 8) * n_dst + row] = cnt;
    }
}

// ---------------------------------------------------------------------------
// Fused gather kernel, 512 blocks x 1024 threads.
//   [0,256)   tract A: tile = b>>1, dstblk = b&1
//   [256,384) tract B;  [384,512) tract C
// Staging: cp.async 4B, warp w -> tokens {2w,2w+1}, lane -> src. 2-stage pipe.
// Gather:  warp-uniform dst, lane = token pair (LDS.64, conflict-free).
// ---------------------------------------------------------------------------
__global__ __launch_bounds__(1024, 1)
void tract_fused(const float* __restrict__ xa,
                 const float* __restrict__ xb,
                 const float* __restrict__ xc,
                 float* __restrict__ out)
{
    extern __shared__ float xs[];
    const int tid  = threadIdx.x;
    const int lane = tid & 31;
    const int wid  = tid >> 5;

    // ---- block -> (tract, tile, dst block) dispatch ----
    const float* x; const int2* tab; const int* spl;
    int src, conn, passes, n_dst, col_off, token0, dst_base;
    int b = blockIdx.x;
    if (b < 256) {
        x = xa; tab = g_tabA; spl = g_splA;
        src = 4096; conn = 64; passes = 16; n_dst = 1024;
        col_off = 0; token0 = (b >> 1) * TOKS; dst_base = (b & 1) * NDST;
    } else if (b < 384) {
        x = xb; tab = g_tabB; spl = g_splB;
        src = 4096; conn = 64; passes = 16; n_dst = 512;
        col_off = 1024; token0 = (b - 256) * TOKS; dst_base = 0;
    } else {
        x = xc; tab = g_tabC; spl = g_splC;
        src = 2048; conn = 32; passes = 8; n_dst = 512;
        col_off = 1536; token0 = (b - 384) * TOKS; dst_base = 0;
    }

    const int dstw = dst_base + wid * DPW;
    const float* xr0_base = x + (size_t)(token0 + 2 * wid) * src;

    // ---- staging macro: chunk p into buffer buf ----
#define STAGE(p, buf) do {                                                   \
        const float* _r0 = xr0_base + (p) * CHUNK;                           \
        const float* _r1 = _r0 + src;                                        \
        float* _d = xs + (buf) * BUFW + 2 * wid;                             \
        _Pragma("unroll")                                                    \
        for (int _s = 0; _s < CHUNK; _s += 32) {                             \
            cp_async4(_d + (_s + lane) * S,     _r0 + _s + lane);            \
            cp_async4(_d + (_s + lane) * S + 1, _r1 + _s + lane);            \
        }                                                                    \
        cp_commit();                                                         \
    } while (0)

    float2 acc[DPW];
#pragma unroll
    for (int d = 0; d < DPW; d++) acc[d] = make_float2(0.0f, 0.0f);

    STAGE(0, 0);
    STAGE(1, 1);

    int e_cur = 0;                          // lane (d&15): segment start
    const int2* tab_w = tab + (size_t)dstw * conn;

    for (int p = 0; p < passes; p++) {
        int e_nxt = spl[(p + 1) * n_dst + dstw + (lane & 15)];

        if (p + 1 < passes) cp_wait1(); else cp_wait0();
        __syncthreads();                    // chunk p visible to all warps

        const float* buf = xs + (p & 1) * BUFW + 2 * lane;
#pragma unroll
        for (int d = 0; d < DPW; d++) {
            int e0 = __shfl_sync(0xffffffffu, e_cur, d);
            int e1 = __shfl_sync(0xffffffffu, e_nxt, d);
            const int2* t = tab_w + d * conn;
            float a0x = 0.f, a0y = 0.f, a1x = 0.f, a1y = 0.f;
            int e = e0;
            for (; e + 1 < e1; e += 2) {
                int2 qa = t[e];
                int2 qb = t[e + 1];
                float2 xv0 = *(const float2*)(buf + qa.x);
                float2 xv1 = *(const float2*)(buf + qb.x);
                float w0 = __int_as_float(qa.y);
                float w1 = __int_as_float(qb.y);
                a0x = fmaf(w0, xv0.x, a0x);
                a0y = fmaf(w0, xv0.y, a0y);
                a1x = fmaf(w1, xv1.x, a1x);
                a1y = fmaf(w1, xv1.y, a1y);
            }
            if (e < e1) {
                int2 qa = t[e];
                float2 xv0 = *(const float2*)(buf + qa.x);
                float w0 = __int_as_float(qa.y);
                a0x = fmaf(w0, xv0.x, a0x);
                a0y = fmaf(w0, xv0.y, a0y);
            }
            acc[d].x += a0x + a1x;
            acc[d].y += a0y + a1y;
        }
        e_cur = e_nxt;

        __syncthreads();                    // all done reading buf (p&1)
        if (p + 2 < passes) STAGE(p + 2, p & 1);
    }

    // ---- transpose through SMEM (even offsets -> aligned), coalesced store ----
    __syncthreads();
#pragma unroll
    for (int d = 0; d < DPW; d++) {
        int dl = wid * DPW + d;             // local dst 0..511
        *(float2*)&xs[dl * S + 2 * lane] = acc[d];
    }
    __syncthreads();

    const int total = NDST * TOKS;          // 32768
    for (int i = tid; i < total; i += 1024) {
        int t = i >> 9;                     // token within tile (0..63)
        int c = i & (NDST - 1);             // local dst
        out[(size_t)(token0 + t) * 2048 + col_off + dst_base + c] = xs[c * S + t];
    }
#undef STAGE
}

// ---------------------------------------------------------------------------
// Launch
// ---------------------------------------------------------------------------
extern "C" void kernel_launch(void* const* d_in, const int* in_sizes, int n_in,
                              void* d_out, int out_size)
{
    // Layout detection: dict order vs signature order (w/m swap harmless).
    const float *xa, *wa, *ma, *xb, *wb, *mb, *xc, *wc, *mc;
    if (in_sizes[1] == 1024 * 4096) {           // dict order
        xa = (const float*)d_in[0]; wa = (const float*)d_in[1]; ma = (const float*)d_in[2];
        xb = (const float*)d_in[3]; wb = (const float*)d_in[4]; mb = (const float*)d_in[5];
        xc = (const float*)d_in[6]; wc = (const float*)d_in[7]; mc = (const float*)d_in[8];
    } else {                                    // signature order
        xa = (const float*)d_in[0]; xb = (const float*)d_in[1]; xc = (const float*)d_in[2];
        wa = (const float*)d_in[3]; wb = (const float*)d_in[4]; wc = (const float*)d_in[5];
        ma = (const float*)d_in[6]; mb = (const float*)d_in[7]; mc = (const float*)d_in[8];
    }
    float* out = (float*)d_out;

    cudaFuncSetAttribute(tract_fused, cudaFuncAttributeMaxDynamicSharedMemorySize,
                         SMEM_BYTES);

    // ---- one merged prep launch: 2048 warp-rows, 8 warps per block ----
    prep_all<<<256, 256>>>(wa, ma, wb, mb, wc, mc);

    // ---- fused sparse gather for all three tracts ----
    tract_fused<<<512, 1024, SMEM_BYTES>>>(xa, xb, xc, out);
}

// round 5
// speedup vs baseline: 1.1109x; 1.1109x over previous
#include <cuda_runtime.h>
#include <cstdint>

// ---------------------------------------------------------------------------
// TractBundle: out = concat( x_a @ (Wa*Ma)^T, x_b @ (Wb*Mb)^T, x_c @ (Wc*Mc)^T )
// Masks: 64/64/32-sparse per row -> compressed sparse-gather.
// Register-pipelined LDG->STS staging overlapped with gather (no cp.async).
// S must be EVEN: float2 smem accesses at word offset row*S + 2*lane.
// ---------------------------------------------------------------------------

#define CHUNK 256                   // src elements staged per pass
#define HALF  128                   // staging half-chunk
#define S     66                    // smem row stride (EVEN: float2 alignment)
#define TOKS  64                    // tokens per block (2 per lane, float2)
#define NDST  512                   // dst columns per block
#define DPW   16                    // dsts per warp
#define BUFW  (CHUNK * S)           // 16896 floats per buffer
#define SMEM_BYTES (2 * BUFW * 4)   // 135168

// Compressed tables: entry = ( (src&255)*66 , bits(w*m) ).
// Splits transposed: spl[p * n_dst + dst], cumulative entry counts.
__device__ __align__(16) int2 g_tabA[1024 * 64];
__device__ __align__(16) int2 g_tabB[512 * 64];
__device__ __align__(16) int2 g_tabC[512 * 32];
__device__ int g_splA[17 * 1024];
__device__ int g_splB[17 * 512];
__device__ int g_splC[9 * 512];

// ---------------------------------------------------------------------------
// Merged prep: one warp per dst row across all three tracts (2048 warp-rows).
// ---------------------------------------------------------------------------
__global__ void prep_all(const float* __restrict__ wa, const float* __restrict__ ma,
                         const float* __restrict__ wb, const float* __restrict__ mb,
                         const float* __restrict__ wc, const float* __restrict__ mc)
{
    int g    = (blockIdx.x * blockDim.x + threadIdx.x) >> 5;
    int lane = threadIdx.x & 31;

    const float *W, *M; int2* tab; int* spl;
    int src, n_dst, conn, row;
    if (g < 1024)      { W = wa; M = ma; tab = g_tabA; spl = g_splA;
                         src = 4096; n_dst = 1024; conn = 64; row = g; }
    else if (g < 1536) { W = wb; M = mb; tab = g_tabB; spl = g_splB;
                         src = 4096; n_dst = 512;  conn = 64; row = g - 1024; }
    else               { W = wc; M = mc; tab = g_tabC; spl = g_splC;
                         src = 2048; n_dst = 512;  conn = 32; row = g - 1536; }

    const float* wr = W + (size_t)row * src;
    const float* mr = M + (size_t)row * src;
    int2* trow = tab + (size_t)row * conn;

    if (lane == 0) spl[row] = 0;            // p = 0
    int cnt = 0;
    for (int s0 = 0; s0 < src; s0 += 32) {
        int s = s0 + lane;
        float mv = mr[s];
        unsigned bits = __ballot_sync(0xffffffffu, mv != 0.0f);
        if (mv != 0.0f) {
            int pos = cnt + __popc(bits & ((1u << lane) - 1u));
            trow[pos] = make_int2((s & (CHUNK - 1)) * S, __float_as_int(wr[s] * mv));
        }
        cnt += __popc(bits);
        int s_end = s0 + 32;
        if ((s_end & (CHUNK - 1)) == 0 && lane == 0)
            spl[(s_end >> 8) * n_dst + row] = cnt;
    }
}

// ---------------------------------------------------------------------------
// Fused gather kernel, 512 blocks x 1024 threads.
//   [0,256)   tract A: tile = b>>1, dstblk = b&1
//   [256,384) tract B;  [384,512) tract C
// Per pass p: gather buf[p&1] while staging chunk p+1 into buf[(p+1)&1]
// through 8 registers (two half-chunks), one __syncthreads per pass.
// ---------------------------------------------------------------------------
__global__ __launch_bounds__(1024, 1)
void tract_fused(const float* __restrict__ xa,
                 const float* __restrict__ xb,
                 const float* __restrict__ xc,
                 float* __restrict__ out)
{
    extern __shared__ float xs[];
    const int tid  = threadIdx.x;
    const int lane = tid & 31;
    const int wid  = tid >> 5;

    // ---- block -> (tract, tile, dst block) dispatch ----
    const float* x; const int2* tab; const int* spl;
    int src, conn, passes, n_dst, col_off, token0, dst_base;
    int b = blockIdx.x;
    if (b < 256) {
        x = xa; tab = g_tabA; spl = g_splA;
        src = 4096; conn = 64; passes = 16; n_dst = 1024;
        col_off = 0; token0 = (b >> 1) * TOKS; dst_base = (b & 1) * NDST;
    } else if (b < 384) {
        x = xb; tab = g_tabB; spl = g_splB;
        src = 4096; conn = 64; passes = 16; n_dst = 512;
        col_off = 1024; token0 = (b - 256) * TOKS; dst_base = 0;
    } else {
        x = xc; tab = g_tabC; spl = g_splC;
        src = 2048; conn = 32; passes = 8; n_dst = 512;
        col_off = 1536; token0 = (b - 384) * TOKS; dst_base = 0;
    }

    const int dstw = dst_base + wid * DPW;
    const int2* tab_w = tab + (size_t)dstw * conn;
    // thread stages tokens {2*wid, 2*wid+1}, src position = lane within groups
    const float* xr0 = x + (size_t)(token0 + 2 * wid) * src;
    const float* xr1 = xr0 + src;

    float2 st[4];                           // staged half-chunk (8 regs)

    // LDG half h (0/1) of chunk p into st[]
#define LDG_HALF(p, h) do {                                                  \
        int _base = (p) * CHUNK + (h) * HALF + lane;                         \
        _Pragma("unroll")                                                    \
        for (int _i = 0; _i < 4; _i++)                                       \
            st[_i] = make_float2(xr0[_base + _i * 32], xr1[_base + _i * 32]);\
    } while (0)

    // STS st[] as half h into buffer bb
#define STS_HALF(bb, h) do {                                                 \
        float* _d = xs + (bb) * BUFW + 2 * wid;                              \
        _Pragma("unroll")                                                    \
        for (int _i = 0; _i < 4; _i++)                                       \
            *(float2*)&_d[((h) * HALF + lane + _i * 32) * S] = st[_i];       \
    } while (0)

    // gather dsts [d0,d1) of pass p from buf
#define GATHER(d0, d1) do {                                                  \
        _Pragma("unroll")                                                    \
        for (int d = (d0); d < (d1); d++) {                                  \
            int e  = __shfl_sync(0xffffffffu, e_cur, d);                     \
            int e1 = __shfl_sync(0xffffffffu, e_nxt, d);                     \
            const int2* t = tab_w + d * conn;                                \
            float a0x = 0.f, a0y = 0.f, a1x = 0.f, a1y = 0.f;                \
            for (; e + 1 < e1; e += 2) {                                     \
                int2 qa = t[e];                                              \
                int2 qb = t[e + 1];                                          \
                float2 xv0 = *(const float2*)(buf + qa.x);                   \
                float2 xv1 = *(const float2*)(buf + qb.x);                   \
                float w0 = __int_as_float(qa.y);                             \
                float w1 = __int_as_float(qb.y);                             \
                a0x = fmaf(w0, xv0.x, a0x);                                  \
                a0y = fmaf(w0, xv0.y, a0y);                                  \
                a1x = fmaf(w1, xv1.x, a1x);                                  \
                a1y = fmaf(w1, xv1.y, a1y);                                  \
            }                                                                \
            if (e < e1) {                                                    \
                int2 qa = t[e];                                              \
                float2 xv0 = *(const float2*)(buf + qa.x);                   \
                float w0 = __int_as_float(qa.y);                             \
                a0x = fmaf(w0, xv0.x, a0x);                                  \
                a0y = fmaf(w0, xv0.y, a0y);                                  \
            }                                                                \
            acc[d].x += a0x + a1x;                                           \
            acc[d].y += a0y + a1y;                                           \
        }                                                                    \
    } while (0)

    float2 acc[DPW];
#pragma unroll
    for (int d = 0; d < DPW; d++) acc[d] = make_float2(0.0f, 0.0f);

    // ---- prologue: stage chunk 0 into buf 0 ----
    LDG_HALF(0, 0); STS_HALF(0, 0);
    LDG_HALF(0, 1); STS_HALF(0, 1);
    __syncthreads();

    int e_cur = 0;                          // lane (d&15): running segment start

    for (int p = 0; p < passes; p++) {
        int e_nxt = spl[(p + 1) * n_dst + dstw + (lane & 15)];
        const bool more = (p + 1 < passes);
        const int nb = (p + 1) & 1;         // buffer being filled
        const float* buf = xs + (p & 1) * BUFW + 2 * lane;

        if (more) LDG_HALF(p + 1, 0);       // latency hidden by gather below
        GATHER(0, DPW / 2);
        if (more) { STS_HALF(nb, 0); LDG_HALF(p + 1, 1); }
        GATHER(DPW / 2, DPW);
        if (more) STS_HALF(nb, 1);

        e_cur = e_nxt;
        __syncthreads();                    // chunk p+1 complete; buf p released
    }

    // ---- transpose through SMEM (even offsets -> aligned), coalesced store ----
#pragma unroll
    for (int d = 0; d < DPW; d++) {
        int dl = wid * DPW + d;             // local dst 0..511
        *(float2*)&xs[dl * S + 2 * lane] = acc[d];
    }
    __syncthreads();

    const int total = NDST * TOKS;          // 32768
    for (int i = tid; i < total; i += 1024) {
        int t = i >> 9;                     // token within tile (0..63)
        int c = i & (NDST - 1);             // local dst
        out[(size_t)(token0 + t) * 2048 + col_off + dst_base + c] = xs[c * S + t];
    }
#undef LDG_HALF
#undef STS_HALF
#undef GATHER
}

// ---------------------------------------------------------------------------
// Launch
// ---------------------------------------------------------------------------
extern "C" void kernel_launch(void* const* d_in, const int* in_sizes, int n_in,
                              void* d_out, int out_size)
{
    // Layout detection: dict order vs signature order (w/m swap harmless).
    const float *xa, *wa, *ma, *xb, *wb, *mb, *xc, *wc, *mc;
    if (in_sizes[1] == 1024 * 4096) {           // dict order
        xa = (const float*)d_in[0]; wa = (const float*)d_in[1]; ma = (const float*)d_in[2];
        xb = (const float*)d_in[3]; wb = (const float*)d_in[4]; mb = (const float*)d_in[5];
        xc = (const float*)d_in[6]; wc = (const float*)d_in[7]; mc = (const float*)d_in[8];
    } else {                                    // signature order
        xa = (const float*)d_in[0]; xb = (const float*)d_in[1]; xc = (const float*)d_in[2];
        wa = (const float*)d_in[3]; wb = (const float*)d_in[4]; wc = (const float*)d_in[5];
        ma = (const float*)d_in[6]; mb = (const float*)d_in[7]; mc = (const float*)d_in[8];
    }
    float* out = (float*)d_out;

    cudaFuncSetAttribute(tract_fused, cudaFuncAttributeMaxDynamicSharedMemorySize,
                         SMEM_BYTES);

    // ---- one merged prep launch: 2048 warp-rows, 8 warps per block ----
    prep_all<<<256, 256>>>(wa, ma, wb, mb, wc, mc);

    // ---- fused sparse gather for all three tracts ----
    tract_fused<<<512, 1024, SMEM_BYTES>>>(xa, xb, xc, out);
}